// round 1
// baseline (speedup 1.0000x reference)
#include <cuda_runtime.h>
#include <cuda_bf16.h>
#include <math.h>

#define Bc 64
#define Sc 128
#define Tc 64
#define Hc 512
#define Vc 32000

// ---------------- scratch (device globals: no allocs allowed) ----------------
__device__ float g_Uk[(size_t)Bc * Sc * Hc];   // 16 MB: Ua(keys) precompute
__device__ float g_h[Bc * Hc];                 // hidden state
__device__ float g_ctx[Bc * Hc];               // attention context

__device__ __forceinline__ float sigm(float x) { return 1.0f / (1.0f + expf(-x)); }

// ---------------- init / final copies ----------------
__global__ void init_h_kernel(const float* __restrict__ src) {
    int i = blockIdx.x * 256 + threadIdx.x;
    if (i < Bc * Hc) g_h[i] = src[i];
}
__global__ void final_h_kernel(float* __restrict__ dst) {
    int i = blockIdx.x * 256 + threadIdx.x;
    if (i < Bc * Hc) dst[i] = g_h[i];
}

// ---------------- Uk = enc @ Ua + bu  (NN GEMM, M=8192,N=512,K=512) ----------
__global__ __launch_bounds__(256) void uk_gemm_kernel(
    const float* __restrict__ A,   // enc [8192,512]
    const float* __restrict__ Bm,  // Ua  [512,512]
    const float* __restrict__ bias)
{
    __shared__ float As[32][65];
    __shared__ float Bs[32][65];
    const int K = Hc, N = Hc;
    int tx = threadIdx.x & 15, ty = threadIdx.x >> 4;
    int n0 = blockIdx.x * 64, m0 = blockIdx.y * 64;
    float acc[4][4] = {};
    for (int k0 = 0; k0 < K; k0 += 32) {
        for (int i = threadIdx.x; i < 64 * 32; i += 256) {
            int r = i >> 5, kk = i & 31;
            As[kk][r] = A[(size_t)(m0 + r) * K + k0 + kk];
        }
        for (int i = threadIdx.x; i < 32 * 64; i += 256) {
            int kk = i >> 6, c = i & 63;
            Bs[kk][c] = Bm[(size_t)(k0 + kk) * N + n0 + c];
        }
        __syncthreads();
#pragma unroll
        for (int kk = 0; kk < 32; kk++) {
            float a[4], bb[4];
#pragma unroll
            for (int i = 0; i < 4; i++) a[i] = As[kk][ty * 4 + i];
#pragma unroll
            for (int j = 0; j < 4; j++) bb[j] = Bs[kk][tx * 4 + j];
#pragma unroll
            for (int i = 0; i < 4; i++)
#pragma unroll
                for (int j = 0; j < 4; j++) acc[i][j] += a[i] * bb[j];
        }
        __syncthreads();
    }
#pragma unroll
    for (int i = 0; i < 4; i++) {
        int r = m0 + ty * 4 + i;
#pragma unroll
        for (int j = 0; j < 4; j++) {
            int c = n0 + tx * 4 + j;
            g_Uk[(size_t)r * N + c] = acc[i][j] + bias[c];
        }
    }
}

// ---------------- per-step attention (one block per batch row) ----------------
// hWa = h@Wa+ba ; scores_s = sum_k tanh(hWa_k + Uk[b,s,k]) * Va_k ;
// w = softmax(scores) ; ctx = w @ enc[b] ; writes attn output + g_ctx
__global__ __launch_bounds__(512) void attn_kernel(
    const float* __restrict__ enc, const float* __restrict__ Wa,
    const float* __restrict__ ba, const float* __restrict__ Va,
    float* __restrict__ att_out, int t)
{
    int b = blockIdx.x;
    __shared__ float sh[Hc];
    __shared__ float shWa[Hc];
    __shared__ float sw[Sc];
    int tid = threadIdx.x;
    sh[tid] = g_h[b * Hc + tid];
    __syncthreads();

    // phase 1: hWa[tid]
    {
        float a0 = 0.f, a1 = 0.f, a2 = 0.f, a3 = 0.f;
#pragma unroll 4
        for (int k = 0; k < Hc; k += 4) {
            a0 += sh[k + 0] * Wa[(size_t)(k + 0) * Hc + tid];
            a1 += sh[k + 1] * Wa[(size_t)(k + 1) * Hc + tid];
            a2 += sh[k + 2] * Wa[(size_t)(k + 2) * Hc + tid];
            a3 += sh[k + 3] * Wa[(size_t)(k + 3) * Hc + tid];
        }
        shWa[tid] = ba[tid] + ((a0 + a1) + (a2 + a3));
    }
    __syncthreads();

    // phase 2: scores (16 warps, 8 s each)
    int warp = tid >> 5, lane = tid & 31;
    for (int s = warp; s < Sc; s += 16) {
        const float* uk = g_Uk + ((size_t)b * Sc + s) * Hc;
        float a = 0.f;
#pragma unroll 4
        for (int k = lane; k < Hc; k += 32)
            a += tanhf(shWa[k] + uk[k]) * Va[k];
#pragma unroll
        for (int o = 16; o; o >>= 1) a += __shfl_xor_sync(0xffffffffu, a, o);
        if (lane == 0) sw[s] = a;   // bv cancels in softmax
    }
    __syncthreads();

    // phase 3: softmax over S=128 inside warp 0
    if (warp == 0) {
        float v0 = sw[lane], v1 = sw[lane + 32], v2 = sw[lane + 64], v3 = sw[lane + 96];
        float m = fmaxf(fmaxf(v0, v1), fmaxf(v2, v3));
#pragma unroll
        for (int o = 16; o; o >>= 1) m = fmaxf(m, __shfl_xor_sync(0xffffffffu, m, o));
        float e0 = expf(v0 - m), e1 = expf(v1 - m), e2 = expf(v2 - m), e3 = expf(v3 - m);
        float s = e0 + e1 + e2 + e3;
#pragma unroll
        for (int o = 16; o; o >>= 1) s += __shfl_xor_sync(0xffffffffu, s, o);
        float inv = 1.0f / s;
        sw[lane] = e0 * inv; sw[lane + 32] = e1 * inv;
        sw[lane + 64] = e2 * inv; sw[lane + 96] = e3 * inv;
    }
    __syncthreads();

    if (tid < Sc) att_out[((size_t)b * Tc + t) * Sc + tid] = sw[tid];

    // phase 4: ctx[tid]
    {
        const float* encb = enc + (size_t)b * Sc * Hc;
        float c0 = 0.f, c1 = 0.f;
#pragma unroll 4
        for (int s = 0; s < Sc; s += 2) {
            c0 += sw[s] * encb[(size_t)s * Hc + tid];
            c1 += sw[s + 1] * encb[(size_t)(s + 1) * Hc + tid];
        }
        g_ctx[b * Hc + tid] = c0 + c1;
    }
}

// ---------------- per-step GRU (one block per batch row, 1024 thr) -----------
__global__ __launch_bounds__(1024) void gru_kernel(
    const float* __restrict__ emb, const int* __restrict__ tgt,
    const float* __restrict__ W_ih, const float* __restrict__ W_hh,
    const float* __restrict__ b_ih, const float* __restrict__ b_hh, int t)
{
    int b = blockIdx.x;
    __shared__ float xs[2 * Hc];   // [e | ctx]
    __shared__ float hs[Hc];
    __shared__ float sgi[3 * Hc];
    __shared__ float sgh[3 * Hc];
    int tid = threadIdx.x;
    int tok = (t == 0) ? 0 : tgt[b * Tc + t - 1];
    if (tid < Hc) {
        xs[tid] = emb[(size_t)tok * Hc + tid];
        hs[tid] = g_h[b * Hc + tid];
    } else {
        xs[tid] = g_ctx[b * Hc + (tid - Hc)];
    }
    __syncthreads();

    int warp = tid >> 5, lane = tid & 31;  // 32 warps
    for (int j = warp; j < 3 * Hc; j += 32) {
        const float* wi = W_ih + (size_t)j * (2 * Hc);
        const float* wh = W_hh + (size_t)j * Hc;
        float ai = 0.f, ah = 0.f;
#pragma unroll 4
        for (int k = lane; k < 2 * Hc; k += 32) ai += xs[k] * wi[k];
#pragma unroll 4
        for (int k = lane; k < Hc; k += 32) ah += hs[k] * wh[k];
#pragma unroll
        for (int o = 16; o; o >>= 1) {
            ai += __shfl_xor_sync(0xffffffffu, ai, o);
            ah += __shfl_xor_sync(0xffffffffu, ah, o);
        }
        if (lane == 0) { sgi[j] = ai + b_ih[j]; sgh[j] = ah + b_hh[j]; }
    }
    __syncthreads();

    if (tid < Hc) {
        float r = sigm(sgi[tid] + sgh[tid]);
        float z = sigm(sgi[Hc + tid] + sgh[Hc + tid]);
        float n = tanhf(sgi[2 * Hc + tid] + r * sgh[2 * Hc + tid]);
        g_h[b * Hc + tid] = (1.0f - z) * n + z * hs[tid];
    }
}

// ---------------- logits = h_new @ Wout^T + bout  (NT GEMM, M=64,N=32000,K=512)
// writes directly into d_out log_probs slice; row stride = T*V
__global__ __launch_bounds__(256) void logits_kernel(
    const float* __restrict__ Wout, const float* __restrict__ bout,
    float* __restrict__ C /* d_out + t*V */)
{
    __shared__ float As[32][65];
    __shared__ float Bs[32][65];
    const int K = Hc;
    int tx = threadIdx.x & 15, ty = threadIdx.x >> 4;
    int n0 = blockIdx.x * 64;
    float acc[4][4] = {};
    for (int k0 = 0; k0 < K; k0 += 32) {
        for (int i = threadIdx.x; i < 64 * 32; i += 256) {
            int r = i >> 5, kk = i & 31;
            As[kk][r] = g_h[r * K + k0 + kk];
            Bs[kk][r] = Wout[(size_t)(n0 + r) * K + k0 + kk];
        }
        __syncthreads();
#pragma unroll
        for (int kk = 0; kk < 32; kk++) {
            float a[4], bb[4];
#pragma unroll
            for (int i = 0; i < 4; i++) a[i] = As[kk][ty * 4 + i];
#pragma unroll
            for (int j = 0; j < 4; j++) bb[j] = Bs[kk][tx * 4 + j];
#pragma unroll
            for (int i = 0; i < 4; i++)
#pragma unroll
                for (int j = 0; j < 4; j++) acc[i][j] += a[i] * bb[j];
        }
        __syncthreads();
    }
    const size_t ldc = (size_t)Tc * Vc;
#pragma unroll
    for (int i = 0; i < 4; i++) {
        int r = ty * 4 + i;           // batch row
#pragma unroll
        for (int j = 0; j < 4; j++) {
            int c = n0 + tx * 4 + j;  // vocab col
            C[(size_t)r * ldc + c] = acc[i][j] + bout[c];
        }
    }
}

// ---------------- in-place log_softmax over V per batch row ------------------
__global__ __launch_bounds__(256) void lsm_kernel(float* __restrict__ Cbase /* d_out + t*V */)
{
    int b = blockIdx.x;
    float* row = Cbase + (size_t)b * Tc * Vc;
    __shared__ float red[8];
    int tid = threadIdx.x, lane = tid & 31, w = tid >> 5;

    float m = -3.4e38f;
    for (int v = tid; v < Vc; v += 256) m = fmaxf(m, row[v]);
#pragma unroll
    for (int o = 16; o; o >>= 1) m = fmaxf(m, __shfl_xor_sync(0xffffffffu, m, o));
    if (lane == 0) red[w] = m;
    __syncthreads();
    float bm = red[0];
#pragma unroll
    for (int i = 1; i < 8; i++) bm = fmaxf(bm, red[i]);
    __syncthreads();

    float s = 0.f;
    for (int v = tid; v < Vc; v += 256) s += __expf(row[v] - bm);
#pragma unroll
    for (int o = 16; o; o >>= 1) s += __shfl_xor_sync(0xffffffffu, s, o);
    if (lane == 0) red[w] = s;
    __syncthreads();
    float tot = 0.f;
#pragma unroll
    for (int i = 0; i < 8; i++) tot += red[i];

    float ls = bm + logf(tot);
    for (int v = tid; v < Vc; v += 256) row[v] -= ls;
}

// ---------------- launch ----------------
extern "C" void kernel_launch(void* const* d_in, const int* in_sizes, int n_in,
                              void* d_out, int out_size)
{
    const float* enc  = (const float*)d_in[0];
    const float* h0   = (const float*)d_in[1];
    const int*   tgt  = (const int*)d_in[2];
    const float* emb  = (const float*)d_in[3];
    const float* Wa   = (const float*)d_in[4];
    const float* ba   = (const float*)d_in[5];
    const float* Ua   = (const float*)d_in[6];
    const float* bu   = (const float*)d_in[7];
    const float* Va   = (const float*)d_in[8];
    /* d_in[9] = bv : cancels inside softmax, never observable */
    const float* W_ih = (const float*)d_in[10];
    const float* W_hh = (const float*)d_in[11];
    const float* b_ih = (const float*)d_in[12];
    const float* b_hh = (const float*)d_in[13];
    const float* Wout = (const float*)d_in[14];
    const float* bout = (const float*)d_in[15];

    float* out  = (float*)d_out;
    float* logp = out;                                    // [B,T,V]
    float* hf   = out + (size_t)Bc * Tc * Vc;             // [1,B,H]
    float* att  = hf + (size_t)Bc * Hc;                   // [B,T,S]

    // Uk precompute: [B*S, H] = enc @ Ua + bu
    dim3 gUk(Hc / 64, (Bc * Sc) / 64);
    uk_gemm_kernel<<<gUk, 256>>>(enc, Ua, bu);

    // h <- encoder_hidden[0]
    init_h_kernel<<<(Bc * Hc + 255) / 256, 256>>>(h0);

    for (int t = 0; t < Tc; t++) {
        attn_kernel<<<Bc, 512>>>(enc, Wa, ba, Va, att, t);
        gru_kernel<<<Bc, 1024>>>(emb, tgt, W_ih, W_hh, b_ih, b_hh, t);
        logits_kernel<<<Vc / 64, 256>>>(Wout, bout, logp + (size_t)t * Vc);
        lsm_kernel<<<Bc, 256>>>(logp + (size_t)t * Vc);
    }

    final_h_kernel<<<(Bc * Hc + 255) / 256, 256>>>(hf);
}

// round 2
// speedup vs baseline: 1.0642x; 1.0642x over previous
#include <cuda_runtime.h>
#include <cuda_bf16.h>
#include <math.h>

#define Bc 64
#define Sc 128
#define Tc 64
#define Hc 512
#define Vc 32000

// ---------------- scratch (device globals: no allocs allowed) ----------------
__device__ float g_Uk[(size_t)Bc * Sc * Hc];   // 16 MB: Ua(keys) precompute
__device__ float g_h[Bc * Hc];                 // hidden state
__device__ float g_ctx[Bc * Hc];               // attention context
__device__ float g_hwa[Bc * Hc];               // h@Wa + ba
__device__ float g_scores[Bc * Sc];            // attention scores
__device__ float g_gi[Bc * 3 * Hc];            // x@W_ih^T
__device__ float g_gh[Bc * 3 * Hc];            // h@W_hh^T

__device__ __forceinline__ float sigm(float x) { return 1.0f / (1.0f + expf(-x)); }

// ---------------- init / final copies ----------------
__global__ void init_h_kernel(const float* __restrict__ src) {
    int i = blockIdx.x * 256 + threadIdx.x;
    if (i < Bc * Hc) g_h[i] = src[i];
}
__global__ void final_h_kernel(float* __restrict__ dst) {
    int i = blockIdx.x * 256 + threadIdx.x;
    if (i < Bc * Hc) dst[i] = g_h[i];
}

// ---------------- Uk = enc @ Ua + bu  (NN GEMM, M=8192,N=512,K=512) ----------
__global__ __launch_bounds__(256) void uk_gemm_kernel(
    const float* __restrict__ A,   // enc [8192,512]
    const float* __restrict__ Bm,  // Ua  [512,512]
    const float* __restrict__ bias)
{
    __shared__ float As[32][68];
    __shared__ float Bs[32][68];
    const int K = Hc, N = Hc;
    int tx = threadIdx.x & 15, ty = threadIdx.x >> 4;
    int n0 = blockIdx.x * 64, m0 = blockIdx.y * 64;
    float acc[4][4] = {};
    for (int k0 = 0; k0 < K; k0 += 32) {
        for (int i = threadIdx.x; i < 64 * 32; i += 256) {
            int r = i >> 5, kk = i & 31;
            As[kk][r] = A[(size_t)(m0 + r) * K + k0 + kk];
        }
        for (int i = threadIdx.x; i < 32 * 64; i += 256) {
            int kk = i >> 6, c = i & 63;
            Bs[kk][c] = Bm[(size_t)(k0 + kk) * N + n0 + c];
        }
        __syncthreads();
#pragma unroll
        for (int kk = 0; kk < 32; kk++) {
            float4 a = *(const float4*)&As[kk][ty * 4];
            float4 b = *(const float4*)&Bs[kk][tx * 4];
            float av[4] = {a.x, a.y, a.z, a.w};
            float bv[4] = {b.x, b.y, b.z, b.w};
#pragma unroll
            for (int i = 0; i < 4; i++)
#pragma unroll
                for (int j = 0; j < 4; j++) acc[i][j] += av[i] * bv[j];
        }
        __syncthreads();
    }
#pragma unroll
    for (int i = 0; i < 4; i++) {
        int r = m0 + ty * 4 + i;
#pragma unroll
        for (int j = 0; j < 4; j++) {
            int c = n0 + tx * 4 + j;
            g_Uk[(size_t)r * N + c] = acc[i][j] + bias[c];
        }
    }
}

// ---------------- hwa = h @ Wa + ba  (NN GEMM, M=64,N=512,K=512) -------------
// grid 16 blocks (N-tile 32), 256 threads, thread tile 4x2
__global__ __launch_bounds__(256) void hwa_kernel(
    const float* __restrict__ Wa, const float* __restrict__ ba)
{
    __shared__ float As[32][68];
    __shared__ float Bs[32][36];
    int tid = threadIdx.x;
    int tx = tid & 15, ty = tid >> 4;
    int n0 = blockIdx.x * 32;
    float acc[4][2] = {};
    for (int k0 = 0; k0 < Hc; k0 += 32) {
        for (int i = tid; i < 64 * 32; i += 256) {
            int r = i >> 5, kk = i & 31;
            As[kk][r] = g_h[r * Hc + k0 + kk];
        }
        for (int i = tid; i < 32 * 32; i += 256) {
            int kk = i >> 5, c = i & 31;
            Bs[kk][c] = Wa[(size_t)(k0 + kk) * Hc + n0 + c];
        }
        __syncthreads();
#pragma unroll
        for (int kk = 0; kk < 32; kk++) {
            float4 a = *(const float4*)&As[kk][ty * 4];
            float2 b = *(const float2*)&Bs[kk][tx * 2];
            acc[0][0] += a.x * b.x; acc[0][1] += a.x * b.y;
            acc[1][0] += a.y * b.x; acc[1][1] += a.y * b.y;
            acc[2][0] += a.z * b.x; acc[2][1] += a.z * b.y;
            acc[3][0] += a.w * b.x; acc[3][1] += a.w * b.y;
        }
        __syncthreads();
    }
#pragma unroll
    for (int i = 0; i < 4; i++) {
        int r = ty * 4 + i;
#pragma unroll
        for (int j = 0; j < 2; j++) {
            int c = n0 + tx * 2 + j;
            g_hwa[r * Hc + c] = acc[i][j] + ba[c];
        }
    }
}

// ---------------- scores[b][s] = sum_k tanh(hwa[b][k]+Uk[b][s][k])*Va[k] -----
// grid (8 chunks, 64 b), 128 threads (4 warps, 4 s each)
__global__ __launch_bounds__(128) void scores_kernel(const float* __restrict__ Va)
{
    int b = blockIdx.y, chunk = blockIdx.x;
    __shared__ float shwa[Hc];
    __shared__ float sva[Hc];
    int tid = threadIdx.x;
    for (int i = tid; i < Hc; i += 128) {
        shwa[i] = g_hwa[b * Hc + i];
        sva[i] = Va[i];
    }
    __syncthreads();
    int warp = tid >> 5, lane = tid & 31;
#pragma unroll
    for (int si = 0; si < 4; si++) {
        int s = chunk * 16 + warp * 4 + si;
        const float* uk = g_Uk + ((size_t)b * Sc + s) * Hc;
        float a0 = 0.f, a1 = 0.f;
#pragma unroll 4
        for (int k = lane; k < Hc; k += 64) {
            a0 += tanhf(shwa[k] + uk[k]) * sva[k];
            a1 += tanhf(shwa[k + 32] + uk[k + 32]) * sva[k + 32];
        }
        float a = a0 + a1;
#pragma unroll
        for (int o = 16; o; o >>= 1) a += __shfl_xor_sync(0xffffffffu, a, o);
        if (lane == 0) g_scores[b * Sc + s] = a;   // bv cancels in softmax
    }
}

// ---------------- softmax + ctx  (grid 64, 512 threads) ----------------------
__global__ __launch_bounds__(512) void softmax_ctx_kernel(
    const float* __restrict__ enc, float* __restrict__ att_out, int t)
{
    int b = blockIdx.x;
    __shared__ float sw[Sc];
    int tid = threadIdx.x;
    if (tid < Sc) sw[tid] = g_scores[b * Sc + tid];
    __syncthreads();
    int warp = tid >> 5, lane = tid & 31;
    if (warp == 0) {
        float v0 = sw[lane], v1 = sw[lane + 32], v2 = sw[lane + 64], v3 = sw[lane + 96];
        float m = fmaxf(fmaxf(v0, v1), fmaxf(v2, v3));
#pragma unroll
        for (int o = 16; o; o >>= 1) m = fmaxf(m, __shfl_xor_sync(0xffffffffu, m, o));
        float e0 = expf(v0 - m), e1 = expf(v1 - m), e2 = expf(v2 - m), e3 = expf(v3 - m);
        float s = e0 + e1 + e2 + e3;
#pragma unroll
        for (int o = 16; o; o >>= 1) s += __shfl_xor_sync(0xffffffffu, s, o);
        float inv = 1.0f / s;
        sw[lane] = e0 * inv; sw[lane + 32] = e1 * inv;
        sw[lane + 64] = e2 * inv; sw[lane + 96] = e3 * inv;
    }
    __syncthreads();

    if (tid < Sc) att_out[((size_t)b * Tc + t) * Sc + tid] = sw[tid];

    const float* encb = enc + (size_t)b * Sc * Hc;
    float c0 = 0.f, c1 = 0.f;
#pragma unroll 4
    for (int s = 0; s < Sc; s += 2) {
        c0 += sw[s] * encb[(size_t)s * Hc + tid];
        c1 += sw[s + 1] * encb[(size_t)(s + 1) * Hc + tid];
    }
    g_ctx[b * Hc + tid] = c0 + c1;
}

// ---------------- GRU GEMMs: gi = [e|ctx]@W_ih^T, gh = h@W_hh^T --------------
// grid 96: blocks 0..47 -> gi (K=1024), 48..95 -> gh (K=512). 64x32 tiles.
__global__ __launch_bounds__(256) void gru_gemm_kernel(
    const float* __restrict__ emb, const int* __restrict__ tgt,
    const float* __restrict__ W_ih, const float* __restrict__ W_hh, int t)
{
    bool is_gi = blockIdx.x < 48;
    int n0 = (is_gi ? blockIdx.x : blockIdx.x - 48) * 32;
    const int K = is_gi ? 2 * Hc : Hc;
    const float* W = is_gi ? W_ih : W_hh;
    float* out = is_gi ? g_gi : g_gh;

    __shared__ float As[32][68];
    __shared__ float Bs[32][36];
    __shared__ int stok[64];
    int tid = threadIdx.x;
    if (is_gi && tid < 64) stok[tid] = (t == 0) ? 0 : tgt[tid * Tc + t - 1];
    __syncthreads();

    int tx = tid & 15, ty = tid >> 4;
    float acc[4][2] = {};
    for (int k0 = 0; k0 < K; k0 += 32) {
        for (int i = tid; i < 64 * 32; i += 256) {
            int r = i >> 5, kk = i & 31;
            int k = k0 + kk;
            float v;
            if (is_gi)
                v = (k < Hc) ? emb[(size_t)stok[r] * Hc + k] : g_ctx[r * Hc + k - Hc];
            else
                v = g_h[r * Hc + k];
            As[kk][r] = v;
        }
        for (int i = tid; i < 32 * 32; i += 256) {
            int c = i >> 5, kk = i & 31;
            Bs[kk][c] = W[(size_t)(n0 + c) * K + k0 + kk];
        }
        __syncthreads();
#pragma unroll
        for (int kk = 0; kk < 32; kk++) {
            float4 a = *(const float4*)&As[kk][ty * 4];
            float2 b = *(const float2*)&Bs[kk][tx * 2];
            acc[0][0] += a.x * b.x; acc[0][1] += a.x * b.y;
            acc[1][0] += a.y * b.x; acc[1][1] += a.y * b.y;
            acc[2][0] += a.z * b.x; acc[2][1] += a.z * b.y;
            acc[3][0] += a.w * b.x; acc[3][1] += a.w * b.y;
        }
        __syncthreads();
    }
#pragma unroll
    for (int i = 0; i < 4; i++) {
        int r = ty * 4 + i;
#pragma unroll
        for (int j = 0; j < 2; j++) {
            int c = n0 + tx * 2 + j;
            out[r * (3 * Hc) + c] = acc[i][j];
        }
    }
}

// ---------------- GRU gates (grid 64, 512 threads) ---------------------------
__global__ __launch_bounds__(512) void gates_kernel(
    const float* __restrict__ b_ih, const float* __restrict__ b_hh)
{
    int b = blockIdx.x, j = threadIdx.x;
    const float* gi = g_gi + b * 3 * Hc;
    const float* gh = g_gh + b * 3 * Hc;
    float gir = gi[j] + b_ih[j];
    float ghr = gh[j] + b_hh[j];
    float giz = gi[Hc + j] + b_ih[Hc + j];
    float ghz = gh[Hc + j] + b_hh[Hc + j];
    float gin = gi[2 * Hc + j] + b_ih[2 * Hc + j];
    float ghn = gh[2 * Hc + j] + b_hh[2 * Hc + j];
    float r = sigm(gir + ghr);
    float z = sigm(giz + ghz);
    float n = tanhf(gin + r * ghn);
    float hprev = g_h[b * Hc + j];
    g_h[b * Hc + j] = (1.0f - z) * n + z * hprev;
}

// ---------------- logits = h_new @ Wout^T + bout  (NT, M=64,N=32000,K=512) ---
// 64x128 tiles, 250 blocks, 256 threads, thread tile 4x8, float4 smem traffic
__global__ __launch_bounds__(256) void logits_kernel(
    const float* __restrict__ Wout, const float* __restrict__ bout,
    float* __restrict__ C /* d_out + t*V */)
{
    __shared__ float As[32][68];
    __shared__ float Bs[32][132];
    int tid = threadIdx.x;
    int tx = tid & 15, ty = tid >> 4;
    int n0 = blockIdx.x * 128;
    float acc[4][8] = {};
    for (int k0 = 0; k0 < Hc; k0 += 32) {
        // As: 64 rows x 32 k  (512 float4 loads, 2 per thread)
        for (int i = tid; i < 512; i += 256) {
            int r = i >> 3, kq = i & 7;
            float4 v = *(const float4*)&g_h[r * Hc + k0 + kq * 4];
            As[kq * 4 + 0][r] = v.x;
            As[kq * 4 + 1][r] = v.y;
            As[kq * 4 + 2][r] = v.z;
            As[kq * 4 + 3][r] = v.w;
        }
        // Bs: 128 cols x 32 k  (1024 float4 loads, 4 per thread)
        for (int i = tid; i < 1024; i += 256) {
            int c = i >> 3, kq = i & 7;
            float4 v = *(const float4*)&Wout[(size_t)(n0 + c) * Hc + k0 + kq * 4];
            Bs[kq * 4 + 0][c] = v.x;
            Bs[kq * 4 + 1][c] = v.y;
            Bs[kq * 4 + 2][c] = v.z;
            Bs[kq * 4 + 3][c] = v.w;
        }
        __syncthreads();
#pragma unroll
        for (int kk = 0; kk < 32; kk++) {
            float4 a = *(const float4*)&As[kk][ty * 4];
            float4 b0 = *(const float4*)&Bs[kk][tx * 8];
            float4 b1 = *(const float4*)&Bs[kk][tx * 8 + 4];
            float av[4] = {a.x, a.y, a.z, a.w};
            float bv[8] = {b0.x, b0.y, b0.z, b0.w, b1.x, b1.y, b1.z, b1.w};
#pragma unroll
            for (int i = 0; i < 4; i++)
#pragma unroll
                for (int j = 0; j < 8; j++) acc[i][j] += av[i] * bv[j];
        }
        __syncthreads();
    }
    const size_t ldc = (size_t)Tc * Vc;
    float4 bo0 = *(const float4*)&bout[n0 + tx * 8];
    float4 bo1 = *(const float4*)&bout[n0 + tx * 8 + 4];
#pragma unroll
    for (int i = 0; i < 4; i++) {
        int r = ty * 4 + i;
        float* crow = C + (size_t)r * ldc + n0 + tx * 8;
        float4 o0 = make_float4(acc[i][0] + bo0.x, acc[i][1] + bo0.y,
                                acc[i][2] + bo0.z, acc[i][3] + bo0.w);
        float4 o1 = make_float4(acc[i][4] + bo1.x, acc[i][5] + bo1.y,
                                acc[i][6] + bo1.z, acc[i][7] + bo1.w);
        *(float4*)crow = o0;
        *(float4*)(crow + 4) = o1;
    }
}

// ---------------- in-place log_softmax over V per batch row ------------------
__global__ __launch_bounds__(512) void lsm_kernel(float* __restrict__ Cbase)
{
    int b = blockIdx.x;
    float* row = Cbase + (size_t)b * Tc * Vc;
    __shared__ float red[16];
    int tid = threadIdx.x, lane = tid & 31, w = tid >> 5;

    float m = -3.4e38f;
    for (int v = tid; v < Vc; v += 512) m = fmaxf(m, row[v]);
#pragma unroll
    for (int o = 16; o; o >>= 1) m = fmaxf(m, __shfl_xor_sync(0xffffffffu, m, o));
    if (lane == 0) red[w] = m;
    __syncthreads();
    float bm = red[0];
#pragma unroll
    for (int i = 1; i < 16; i++) bm = fmaxf(bm, red[i]);
    __syncthreads();

    float s = 0.f;
    for (int v = tid; v < Vc; v += 512) s += __expf(row[v] - bm);
#pragma unroll
    for (int o = 16; o; o >>= 1) s += __shfl_xor_sync(0xffffffffu, s, o);
    if (lane == 0) red[w] = s;
    __syncthreads();
    float tot = 0.f;
#pragma unroll
    for (int i = 0; i < 16; i++) tot += red[i];

    float ls = bm + logf(tot);
    for (int v = tid; v < Vc; v += 512) row[v] -= ls;
}

// ---------------- launch ----------------
extern "C" void kernel_launch(void* const* d_in, const int* in_sizes, int n_in,
                              void* d_out, int out_size)
{
    const float* enc  = (const float*)d_in[0];
    const float* h0   = (const float*)d_in[1];
    const int*   tgt  = (const int*)d_in[2];
    const float* emb  = (const float*)d_in[3];
    const float* Wa   = (const float*)d_in[4];
    const float* ba   = (const float*)d_in[5];
    const float* Ua   = (const float*)d_in[6];
    const float* bu   = (const float*)d_in[7];
    const float* Va   = (const float*)d_in[8];
    /* d_in[9] = bv : cancels inside softmax, never observable */
    const float* W_ih = (const float*)d_in[10];
    const float* W_hh = (const float*)d_in[11];
    const float* b_ih = (const float*)d_in[12];
    const float* b_hh = (const float*)d_in[13];
    const float* Wout = (const float*)d_in[14];
    const float* bout = (const float*)d_in[15];

    float* out  = (float*)d_out;
    float* logp = out;                                    // [B,T,V]
    float* hf   = out + (size_t)Bc * Tc * Vc;             // [1,B,H]
    float* att  = hf + (size_t)Bc * Hc;                   // [B,T,S]

    // Uk precompute: [B*S, H] = enc @ Ua + bu
    dim3 gUk(Hc / 64, (Bc * Sc) / 64);
    uk_gemm_kernel<<<gUk, 256>>>(enc, Ua, bu);

    // h <- encoder_hidden[0]
    init_h_kernel<<<(Bc * Hc + 255) / 256, 256>>>(h0);

    for (int t = 0; t < Tc; t++) {
        hwa_kernel<<<16, 256>>>(Wa, ba);
        scores_kernel<<<dim3(8, Bc), 128>>>(Va);
        softmax_ctx_kernel<<<Bc, 512>>>(enc, att, t);
        gru_gemm_kernel<<<96, 256>>>(emb, tgt, W_ih, W_hh, t);
        gates_kernel<<<Bc, 512>>>(b_ih, b_hh);
        logits_kernel<<<Vc / 128, 256>>>(Wout, bout, logp + (size_t)t * Vc);
        lsm_kernel<<<Bc, 512>>>(logp + (size_t)t * Vc);
    }

    final_h_kernel<<<(Bc * Hc + 255) / 256, 256>>>(hf);
}